// round 1
// baseline (speedup 1.0000x reference)
#include <cuda_runtime.h>
#include <math.h>

#define BATCH 16
#define H 512
#define W 512
#define HW (H*W)

// Global scratch (allocation-free rule): two ping-pong feature buffers,
// 24 channels each ([0:12) = filter branch, [12:24) = weight branch).
__device__ float g_bufA[(size_t)BATCH * 24 * HW];
__device__ float g_bufB[(size_t)BATCH * 24 * HW];

// ---------------------------------------------------------------------------
// Grouped 3x3 conv, SAME padding, ReLU. CIN in-channels per group, 12 out.
// gridDim.z = BATCH*2 ; group g = z&1 selects weight set (wA / wB).
// Tile: 64 wide x 8 high. Block (16,8): each thread does 4 pixels x 12 cout.
// inSel/outSel: 0 = external pointer, 1 = g_bufA, 2 = g_bufB.
// ---------------------------------------------------------------------------
template<int CIN>
__global__ void __launch_bounds__(128, 4)
conv3x3_kernel(const float* __restrict__ extIn, int inSel, int inC, int inGroupStride,
               int outSel,
               const float* __restrict__ wA, const float* __restrict__ wB)
{
    constexpr int TW = 64, TH = 8, PX = 4, PITCH = 68;

    __shared__ __align__(16) float s_in[CIN][TH + 2][PITCH];
    __shared__ float s_w[12 * CIN * 9];

    const int g = blockIdx.z & 1;
    const int b = blockIdx.z >> 1;

    const float* inBase = (inSel == 1) ? g_bufA : ((inSel == 2) ? g_bufB : extIn);
    float* outBase = (outSel == 1) ? g_bufA : g_bufB;

    const float* __restrict__ wt = g ? wB : wA;
    const float* __restrict__ inp = inBase + ((size_t)b * inC + (size_t)g * inGroupStride) * HW;
    float* __restrict__ outp = outBase + ((size_t)b * 24 + (size_t)g * 12) * HW;

    const int tid = threadIdx.y * 16 + threadIdx.x;

    // weights to shared
    for (int i = tid; i < 12 * CIN * 9; i += 128) s_w[i] = wt[i];

    // input tile (with 1-halo), zero-padded at image borders
    const int x0 = blockIdx.x * TW - 1;
    const int y0 = blockIdx.y * TH - 1;
    for (int i = tid; i < CIN * (TH + 2) * 66; i += 128) {
        int c  = i / ((TH + 2) * 66);
        int r  = i - c * ((TH + 2) * 66);
        int iy = r / 66;
        int ix = r - iy * 66;
        int gy = y0 + iy, gx = x0 + ix;
        float v = 0.0f;
        if ((unsigned)gy < (unsigned)H && (unsigned)gx < (unsigned)W)
            v = inp[(size_t)c * HW + (size_t)gy * W + gx];
        s_in[c][iy][ix] = v;
    }
    __syncthreads();

    float acc[PX][12];
#pragma unroll
    for (int p = 0; p < PX; ++p)
#pragma unroll
        for (int co = 0; co < 12; ++co) acc[p][co] = 0.0f;

    const int bx = threadIdx.x * PX;
    const int ty = threadIdx.y;

    for (int ci = 0; ci < CIN; ++ci) {
#pragma unroll
        for (int ky = 0; ky < 3; ++ky) {
            const float* row = &s_in[ci][ty + ky][bx];
            float4 va = *(const float4*)row;
            float2 vb = *(const float2*)(row + 4);
            float v[6] = {va.x, va.y, va.z, va.w, vb.x, vb.y};
#pragma unroll
            for (int kx = 0; kx < 3; ++kx) {
                const float* wr = &s_w[ci * 9 + ky * 3 + kx];
#pragma unroll
                for (int co = 0; co < 12; ++co) {
                    float wv = wr[co * CIN * 9];
                    acc[0][co] = fmaf(v[kx + 0], wv, acc[0][co]);
                    acc[1][co] = fmaf(v[kx + 1], wv, acc[1][co]);
                    acc[2][co] = fmaf(v[kx + 2], wv, acc[2][co]);
                    acc[3][co] = fmaf(v[kx + 3], wv, acc[3][co]);
                }
            }
        }
    }

    const int oy = blockIdx.y * TH + ty;
    const int ox = blockIdx.x * TW + bx;
#pragma unroll
    for (int co = 0; co < 12; ++co) {
        float4 r;
        r.x = fmaxf(acc[0][co], 0.0f);
        r.y = fmaxf(acc[1][co], 0.0f);
        r.z = fmaxf(acc[2][co], 0.0f);
        r.w = fmaxf(acc[3][co], 0.0f);
        *(float4*)&outp[(size_t)co * HW + (size_t)oy * W + ox] = r;
    }
}

// ---------------------------------------------------------------------------
// Fusion: softmax over weight channels, green interpolation, chroma conv
// (2->6, SAME), green_add, pixel-shuffle to [B,3,1024,1024].
// Tile 32x8 output pixels, 1-pixel halo for the chroma conv.
// ---------------------------------------------------------------------------
__global__ void __launch_bounds__(256, 4)
fuse_kernel(int featSel, const float* __restrict__ mosaic,
            const float* __restrict__ cw, float* __restrict__ out)
{
    __shared__ float s_g0[10][36];
    __shared__ float s_g1[10][36];
    __shared__ float s_d0[10][36];
    __shared__ float s_d1[10][36];
    __shared__ float s_cw[108];

    const int b = blockIdx.z;
    const float* __restrict__ fp = ((featSel == 1) ? g_bufA : g_bufB) + (size_t)b * 24 * HW;
    const float* __restrict__ mp = mosaic + (size_t)b * 4 * HW;

    const int tid = threadIdx.y * 32 + threadIdx.x;
    if (tid < 108) s_cw[tid] = cw[tid];

    const int x0 = blockIdx.x * 32 - 1;
    const int y0 = blockIdx.y * 8 - 1;

    // Stage 1: green (g0, g1) and chroma-conv inputs (d0, d1) over 34x10 region
    for (int i = tid; i < 34 * 10; i += 256) {
        int iy = i / 34;
        int ix = i - iy * 34;
        int gy = y0 + iy, gx = x0 + ix;
        float g0 = 0.f, g1 = 0.f, d0 = 0.f, d1 = 0.f;
        if ((unsigned)gy < (unsigned)H && (unsigned)gx < (unsigned)W) {
            size_t off = (size_t)gy * W + gx;
            float iv[12], wv[12];
#pragma unroll
            for (int c = 0; c < 12; ++c) iv[c] = fp[(size_t)c * HW + off];
#pragma unroll
            for (int c = 0; c < 12; ++c) wv[c] = fp[(size_t)(12 + c) * HW + off];
            float m = wv[0];
#pragma unroll
            for (int c = 1; c < 12; ++c) m = fmaxf(m, wv[c]);
            float s = 0.f, n0 = 0.f, n1 = 0.f;
#pragma unroll
            for (int c = 0; c < 6; ++c) {
                float e = __expf(wv[c] - m);
                s += e; n0 = fmaf(e, iv[c], n0);
            }
#pragma unroll
            for (int c = 6; c < 12; ++c) {
                float e = __expf(wv[c] - m);
                s += e; n1 = fmaf(e, iv[c], n1);
            }
            float inv = 1.0f / s;
            g0 = n0 * inv;
            g1 = n1 * inv;
            d0 = mp[HW + off] - g0;        // mosaic[1] - green_rb[0]
            d1 = mp[2 * HW + off] - g1;    // mosaic[2] - green_rb[1]
        }
        s_g0[iy][ix] = g0;
        s_g1[iy][ix] = g1;
        s_d0[iy][ix] = d0;
        s_d1[iy][ix] = d1;
    }
    __syncthreads();

    // Stage 2: chroma conv + assembly + pixel shuffle (one center pixel/thread)
    const int tx = threadIdx.x, ty = threadIdx.y;
    const int gx = blockIdx.x * 32 + tx;
    const int gy = blockIdx.y * 8 + ty;

    float cd[6] = {0.f, 0.f, 0.f, 0.f, 0.f, 0.f};
#pragma unroll
    for (int ky = 0; ky < 3; ++ky) {
#pragma unroll
        for (int kx = 0; kx < 3; ++kx) {
            float v0 = s_d0[ty + ky][tx + kx];
            float v1 = s_d1[ty + ky][tx + kx];
#pragma unroll
            for (int o = 0; o < 6; ++o) {
                cd[o] = fmaf(v0, s_cw[(o * 2 + 0) * 9 + ky * 3 + kx], cd[o]);
                cd[o] = fmaf(v1, s_cw[(o * 2 + 1) * 9 + ky * 3 + kx], cd[o]);
            }
        }
    }

    size_t off = (size_t)gy * W + gx;
    float m0 = mp[off];
    float m1 = mp[HW + off];
    float m2 = mp[2 * HW + off];
    float m3 = mp[3 * HW + off];
    float g0 = s_g0[ty + 1][tx + 1];
    float g1 = s_g1[ty + 1][tx + 1];

    // green_add = [m0, g1, m3, m0, g0, m3]
    float cp0 = cd[0] + m0;
    float cp1 = cd[1] + g1;
    float cp2 = cd[2] + m3;
    float cp3 = cd[3] + m0;
    float cp4 = cd[4] + g0;
    float cp5 = cd[5] + m3;

    const size_t OP = (size_t)4 * HW;           // 1024*1024 plane
    float* ob = out + (size_t)b * 3 * OP;
    size_t base = (size_t)(2 * gy) * 1024 + (size_t)(2 * gx);

    // R plane: interleave(cp0, m1, cp1, cp2)
    *(float2*)(ob + 0 * OP + base)        = make_float2(cp0, m1);
    *(float2*)(ob + 0 * OP + base + 1024) = make_float2(cp1, cp2);
    // G plane: interleave(m0, g0, g1, m3)
    *(float2*)(ob + 1 * OP + base)        = make_float2(m0, g0);
    *(float2*)(ob + 1 * OP + base + 1024) = make_float2(g1, m3);
    // B plane: interleave(cp3, cp4, m2, cp5)
    *(float2*)(ob + 2 * OP + base)        = make_float2(cp3, cp4);
    *(float2*)(ob + 2 * OP + base + 1024) = make_float2(m2, cp5);
}

// ---------------------------------------------------------------------------
extern "C" void kernel_launch(void* const* d_in, const int* in_sizes, int n_in,
                              void* d_out, int out_size)
{
    const float* mosaic = (const float*)d_in[0];
    const float* fw0 = (const float*)d_in[1];
    const float* fw1 = (const float*)d_in[2];
    const float* fw2 = (const float*)d_in[3];
    const float* ww0 = (const float*)d_in[4];
    const float* ww1 = (const float*)d_in[5];
    const float* ww2 = (const float*)d_in[6];
    const float* cw0 = (const float*)d_in[7];
    float* out = (float*)d_out;

    dim3 cb(16, 8);
    dim3 cg(W / 64, H / 8, BATCH * 2);

    // layer 0: mosaic(4ch) -> bufA(24ch)   [groups share input, offset 0]
    conv3x3_kernel<4><<<cg, cb>>>(mosaic, /*inSel=*/0, /*inC=*/4, /*inGroupStride=*/0,
                                  /*outSel=*/1, fw0, ww0);
    // layer 1: bufA -> bufB, grouped 12->12
    conv3x3_kernel<12><<<cg, cb>>>(nullptr, /*inSel=*/1, /*inC=*/24, /*inGroupStride=*/12,
                                   /*outSel=*/2, fw1, ww1);
    // layer 2: bufB -> bufA, grouped 12->12
    conv3x3_kernel<12><<<cg, cb>>>(nullptr, /*inSel=*/2, /*inC=*/24, /*inGroupStride=*/12,
                                   /*outSel=*/1, fw2, ww2);
    // fusion + pixel shuffle
    dim3 fb(32, 8);
    dim3 fg(W / 32, H / 8, BATCH);
    fuse_kernel<<<fg, fb>>>(/*featSel=*/1, mosaic, cw0, out);
}